// round 1
// baseline (speedup 1.0000x reference)
#include <cuda_runtime.h>
#include <math.h>

#define S 100
#define BATCH 128
#define NW 430500
#define NB 580
#define ES (NW + NB)
#define W12N 25500
#define WOFF2 25500
#define WOFF3 425500

// ---------------- scratch (device globals; no runtime allocation) ----------------
__device__ float g_sigw[NW];
__device__ float g_sigb[NB];
__device__ float g_w12[S * W12N];       // per-sample conv1+conv2 weights
__device__ float g_ball[S * NB];        // per-sample all biases
__device__ float g_h1[S * BATCH * 2880];   // after conv1+relu+pool: [s][b][20][12][12]
__device__ float g_h2[S * BATCH * 800];    // after conv2+relu+pool: [s][b][800] (c*16+y*4+x)
__device__ float g_h3[S * 500 * BATCH];    // after fc1+relu: [s][500][128]
__device__ float g_lsm[S * BATCH * 10];    // per-sample log-softmax

__device__ __forceinline__ float softplusf(float r) {
    return fmaxf(r, 0.0f) + log1pf(expf(-fabsf(r)));
}

// ---------------- kernel 0: softplus(rho) ----------------
__global__ void k_sig(const float* __restrict__ rho_w, const float* __restrict__ rho_b) {
    int i = blockIdx.x * blockDim.x + threadIdx.x;
    if (i < NW) g_sigw[i] = softplusf(rho_w[i]);
    else if (i < NW + NB) g_sigb[i - NW] = softplusf(rho_b[i - NW]);
}

// ---------------- kernel 1: materialize conv weights + all biases ----------------
__global__ void k_wb(const float* __restrict__ e,
                     const float* __restrict__ mu_w,
                     const float* __restrict__ mu_b) {
    int i = blockIdx.x * blockDim.x + threadIdx.x;
    if (i < S * W12N) {
        int s = i / W12N, j = i % W12N;
        g_w12[i] = fmaf(g_sigw[j], e[(long)s * ES + j], mu_w[j]);
    } else {
        int r = i - S * W12N;
        if (r < S * NB) {
            int s = r / NB, j = r % NB;
            g_ball[r] = fmaf(g_sigb[j], e[(long)s * ES + NW + j], mu_b[j]);
        }
    }
}

// ---------------- kernel 2: conv1 + bias + relu + maxpool ----------------
// grid = S*BATCH, block = 288. Thread: one pooled pixel (12x12) x 10 channels.
__global__ void __launch_bounds__(288) k_conv1(const float* __restrict__ x) {
    __shared__ float xs[784];
    __shared__ float ws[500];
    __shared__ float bs[20];
    int blk = blockIdx.x;
    int s = blk / BATCH, b = blk % BATCH;
    int t = threadIdx.x;
    for (int j = t; j < 784; j += 288) xs[j] = x[b * 784 + j];
    for (int j = t; j < 500; j += 288) ws[j] = g_w12[s * W12N + j];
    if (t < 20) bs[t] = g_ball[s * NB + t];
    __syncthreads();

    int pp = t % 144, cg = t / 144;          // cg in {0,1} -> channels cg*10..+9
    int pi = pp / 12, pj = pp % 12;
    float acc[10][4];
#pragma unroll
    for (int k = 0; k < 10; k++) { acc[k][0] = acc[k][1] = acc[k][2] = acc[k][3] = 0.0f; }

    const float* xb = xs + (2 * pi) * 28 + 2 * pj;
#pragma unroll 1
    for (int ky = 0; ky < 5; ky++) {
#pragma unroll
        for (int kx = 0; kx < 5; kx++) {
            float i00 = xb[ky * 28 + kx];
            float i01 = xb[ky * 28 + kx + 1];
            float i10 = xb[(ky + 1) * 28 + kx];
            float i11 = xb[(ky + 1) * 28 + kx + 1];
#pragma unroll
            for (int k = 0; k < 10; k++) {
                float wv = ws[(cg * 10 + k) * 25 + ky * 5 + kx];
                acc[k][0] = fmaf(wv, i00, acc[k][0]);
                acc[k][1] = fmaf(wv, i01, acc[k][1]);
                acc[k][2] = fmaf(wv, i10, acc[k][2]);
                acc[k][3] = fmaf(wv, i11, acc[k][3]);
            }
        }
    }
    float* outp = g_h1 + (long)(s * BATCH + b) * 2880;
#pragma unroll
    for (int k = 0; k < 10; k++) {
        int c = cg * 10 + k;
        float v = fmaxf(fmaxf(acc[k][0], acc[k][1]), fmaxf(acc[k][2], acc[k][3])) + bs[c];
        outp[c * 144 + pp] = fmaxf(v, 0.0f);
    }
}

// ---------------- kernel 3: conv2 + bias + relu + maxpool ----------------
// grid = S*BATCH, block = 160, dynamic smem = input(2880) + weights(25000) + bias(50).
// Thread: one pooled pixel (4x4) x 5 output channels x 4 pool positions.
__global__ void __launch_bounds__(160) k_conv2() {
    extern __shared__ float sm[];
    float* ins = sm;                 // 2880
    float* ws  = sm + 2880;          // 25000
    float* bs  = sm + 2880 + 25000;  // 50
    int blk = blockIdx.x;
    int s = blk / BATCH, b = blk % BATCH;
    int t = threadIdx.x;
    const float* h1p = g_h1 + (long)(s * BATCH + b) * 2880;
    for (int j = t; j < 2880; j += 160) ins[j] = h1p[j];
    const float* wp = g_w12 + s * W12N + 500;
    for (int j = t; j < 25000; j += 160) ws[j] = wp[j];
    if (t < 50) bs[t] = g_ball[s * NB + 20 + t];
    __syncthreads();

    int pp = t % 16, cg = t / 16;    // cg in 0..9 -> channels cg*5..+4
    int pi = pp / 4, pj = pp % 4;
    float acc[5][4];
#pragma unroll
    for (int k = 0; k < 5; k++) { acc[k][0] = acc[k][1] = acc[k][2] = acc[k][3] = 0.0f; }

    const float* ib = ins + (2 * pi) * 12 + 2 * pj;
    const float* wb = ws + cg * 5 * 500;
#pragma unroll 1
    for (int ci = 0; ci < 20; ci++) {
#pragma unroll
        for (int ky = 0; ky < 5; ky++) {
#pragma unroll
            for (int kx = 0; kx < 5; kx++) {
                float i00 = ib[ci * 144 + ky * 12 + kx];
                float i01 = ib[ci * 144 + ky * 12 + kx + 1];
                float i10 = ib[ci * 144 + (ky + 1) * 12 + kx];
                float i11 = ib[ci * 144 + (ky + 1) * 12 + kx + 1];
                int wo = ci * 25 + ky * 5 + kx;
#pragma unroll
                for (int k = 0; k < 5; k++) {
                    float wv = wb[k * 500 + wo];
                    acc[k][0] = fmaf(wv, i00, acc[k][0]);
                    acc[k][1] = fmaf(wv, i01, acc[k][1]);
                    acc[k][2] = fmaf(wv, i10, acc[k][2]);
                    acc[k][3] = fmaf(wv, i11, acc[k][3]);
                }
            }
        }
    }
    float* outp = g_h2 + (long)(s * BATCH + b) * 800;
#pragma unroll
    for (int k = 0; k < 5; k++) {
        int co = cg * 5 + k;
        float v = fmaxf(fmaxf(acc[k][0], acc[k][1]), fmaxf(acc[k][2], acc[k][3])) + bs[co];
        outp[co * 16 + pi * 4 + pj] = fmaxf(v, 0.0f);
    }
}

// ---------------- kernel 4: fc1 (500x800 @ 800x128) + bias + relu ----------------
// grid = (8 mtiles, S), block = 256. BM=64, BN=128, BK=8, thread tile 4x8.
// A generated on the fly: w3 = mu + sig*e. Register double-buffered global loads.
__global__ void __launch_bounds__(256) k_fc1(const float* __restrict__ e,
                                             const float* __restrict__ mu_w) {
    __shared__ float As[8][68];   // padded: transposed A tile [k][m]
    __shared__ float Bs[8][128];  // B tile [k][n]
    int s = blockIdx.y;
    int mt = blockIdx.x;
    int tid = threadIdx.x;
    int tx = tid % 16, ty = tid / 16;
    int m0 = mt * 64;

    const float* eb = e + (long)s * ES + WOFF2;

    int la = tid * 2;              // A: 512 elems, 2 per thread
    int am = la / 8, ak = la % 8;  // (m-local, k-local), ak even
    int bn = tid / 2, bq = (tid % 2) * 4;  // B: one float4 per thread

    float ra0, ra1;
    float rb0, rb1, rb2, rb3;
    {
        int grow = m0 + am;
        if (grow < 500) {
            long ai = (long)grow * 800 + ak;
            ra0 = fmaf(g_sigw[WOFF2 + ai], eb[ai], mu_w[WOFF2 + ai]);
            ra1 = fmaf(g_sigw[WOFF2 + ai + 1], eb[ai + 1], mu_w[WOFF2 + ai + 1]);
        } else { ra0 = 0.0f; ra1 = 0.0f; }
        float4 bv = *(const float4*)(g_h2 + ((long)s * BATCH + bn) * 800 + bq);
        rb0 = bv.x; rb1 = bv.y; rb2 = bv.z; rb3 = bv.w;
    }

    float acc[4][8];
#pragma unroll
    for (int i = 0; i < 4; i++)
#pragma unroll
        for (int j = 0; j < 8; j++) acc[i][j] = 0.0f;

    for (int kt = 0; kt < 100; kt++) {
        As[ak][am] = ra0;
        As[ak + 1][am] = ra1;
        Bs[bq + 0][bn] = rb0;
        Bs[bq + 1][bn] = rb1;
        Bs[bq + 2][bn] = rb2;
        Bs[bq + 3][bn] = rb3;
        __syncthreads();

        if (kt < 99) {
            int k0 = (kt + 1) * 8;
            int grow = m0 + am;
            if (grow < 500) {
                long ai = (long)grow * 800 + k0 + ak;
                ra0 = fmaf(g_sigw[WOFF2 + ai], eb[ai], mu_w[WOFF2 + ai]);
                ra1 = fmaf(g_sigw[WOFF2 + ai + 1], eb[ai + 1], mu_w[WOFF2 + ai + 1]);
            } else { ra0 = 0.0f; ra1 = 0.0f; }
            float4 bv = *(const float4*)(g_h2 + ((long)s * BATCH + bn) * 800 + k0 + bq);
            rb0 = bv.x; rb1 = bv.y; rb2 = bv.z; rb3 = bv.w;
        }

#pragma unroll
        for (int k = 0; k < 8; k++) {
            float a[4], bb[8];
            *(float4*)a = *(const float4*)&As[k][ty * 4];
            *(float4*)bb = *(const float4*)&Bs[k][tx * 8];
            *(float4*)(bb + 4) = *(const float4*)&Bs[k][tx * 8 + 4];
#pragma unroll
            for (int i = 0; i < 4; i++)
#pragma unroll
                for (int j = 0; j < 8; j++)
                    acc[i][j] = fmaf(a[i], bb[j], acc[i][j]);
        }
        __syncthreads();
    }

#pragma unroll
    for (int i = 0; i < 4; i++) {
        int m = m0 + ty * 4 + i;
        if (m < 500) {
            float bias = g_ball[s * NB + 70 + m];
            float* op = g_h3 + ((long)s * 500 + m) * BATCH + tx * 8;
#pragma unroll
            for (int j = 0; j < 8; j++) {
                op[j] = fmaxf(acc[i][j] + bias, 0.0f);
            }
        }
    }
}

// ---------------- kernel 5: fc2 + bias + log_softmax ----------------
// grid = S, block = 128 (one thread per batch element).
__global__ void __launch_bounds__(128) k_fc2(const float* __restrict__ e,
                                             const float* __restrict__ mu_w) {
    __shared__ float ws[5000];
    __shared__ float bs[10];
    int s = blockIdx.x;
    int t = threadIdx.x;
    for (int j = t; j < 5000; j += 128) {
        long gi = (long)WOFF3 + j;
        ws[j] = fmaf(g_sigw[gi], e[(long)s * ES + gi], mu_w[gi]);
    }
    if (t < 10) bs[t] = g_ball[s * NB + 570 + t];
    __syncthreads();

    float acc[10];
#pragma unroll
    for (int o = 0; o < 10; o++) acc[o] = bs[o];

    const float* hp = g_h3 + (long)s * 500 * BATCH + t;
    for (int i = 0; i < 500; i++) {
        float v = hp[(long)i * BATCH];
#pragma unroll
        for (int o = 0; o < 10; o++) acc[o] = fmaf(ws[o * 500 + i], v, acc[o]);
    }

    float m = acc[0];
#pragma unroll
    for (int o = 1; o < 10; o++) m = fmaxf(m, acc[o]);
    float sum = 0.0f;
#pragma unroll
    for (int o = 0; o < 10; o++) sum += expf(acc[o] - m);
    float lse = m + logf(sum);

    float* op = g_lsm + ((long)s * BATCH + t) * 10;
#pragma unroll
    for (int o = 0; o < 10; o++) op[o] = acc[o] - lse;
}

// ---------------- kernel 6: deterministic mean over samples ----------------
__global__ void k_reduce(float* __restrict__ out) {
    int idx = blockIdx.x * blockDim.x + threadIdx.x;
    if (idx >= BATCH * 10) return;
    int b = idx / 10, o = idx % 10;
    float acc = 0.0f;
    for (int s = 0; s < S; s++) acc += g_lsm[((long)s * BATCH + b) * 10 + o];
    out[idx] = acc * (1.0f / (float)S);
}

// ---------------- launch ----------------
extern "C" void kernel_launch(void* const* d_in, const int* in_sizes, int n_in,
                              void* d_out, int out_size) {
    const float* x     = (const float*)d_in[0];
    const float* e     = (const float*)d_in[1];
    const float* mu_w  = (const float*)d_in[2];
    const float* rho_w = (const float*)d_in[3];
    const float* mu_b  = (const float*)d_in[4];
    const float* rho_b = (const float*)d_in[5];
    float* out = (float*)d_out;

    static int smem_set = 0;
    if (!smem_set) {
        cudaFuncSetAttribute(k_conv2, cudaFuncAttributeMaxDynamicSharedMemorySize, 111720);
        smem_set = 1;
    }

    k_sig<<<(ES + 255) / 256, 256>>>(rho_w, rho_b);

    int wb_total = S * W12N + S * NB;
    k_wb<<<(wb_total + 255) / 256, 256>>>(e, mu_w, mu_b);

    k_conv1<<<S * BATCH, 288>>>(x);
    k_conv2<<<S * BATCH, 160, 111720>>>();

    dim3 g1(8, S);
    k_fc1<<<g1, 256>>>(e, mu_w);
    k_fc2<<<S, 128>>>(e, mu_w);
    k_reduce<<<10, 128>>>(out);
}

// round 3
// speedup vs baseline: 1.4519x; 1.4519x over previous
#include <cuda_runtime.h>
#include <math.h>

#define S 100
#define BATCH 128
#define NW 430500
#define NB 580
#define ES (NW + NB)
#define W12N 25500
#define WOFF2 25500
#define WOFF3 425500

// ---------------- scratch (device globals; no runtime allocation) ----------------
__device__ float g_sigw[NW];
__device__ float g_sigb[NB];
__device__ float g_w12[S * W12N];       // per-sample conv1+conv2 weights
__device__ float g_ball[S * NB];        // per-sample all biases
__device__ float g_h1[S * BATCH * 2880];   // after conv1+relu+pool: [s][b][20][12][12]
__device__ float g_h2[S * BATCH * 800];    // after conv2+relu+pool: [s][b][800] (c*16+y*4+x)
__device__ float g_h3[S * 500 * BATCH];    // after fc1+relu: [s][500][128]
__device__ float g_lsm[S * BATCH * 10];    // per-sample log-softmax

__device__ __forceinline__ float softplusf(float r) {
    return fmaxf(r, 0.0f) + log1pf(expf(-fabsf(r)));
}

// ---------------- kernel 0: softplus(rho) ----------------
__global__ void k_sig(const float* __restrict__ rho_w, const float* __restrict__ rho_b) {
    int i = blockIdx.x * blockDim.x + threadIdx.x;
    if (i < NW) g_sigw[i] = softplusf(rho_w[i]);
    else if (i < NW + NB) g_sigb[i - NW] = softplusf(rho_b[i - NW]);
}

// ---------------- kernel 1: materialize conv weights + all biases ----------------
__global__ void k_wb(const float* __restrict__ e,
                     const float* __restrict__ mu_w,
                     const float* __restrict__ mu_b) {
    int i = blockIdx.x * blockDim.x + threadIdx.x;
    if (i < S * W12N) {
        int s = i / W12N, j = i % W12N;
        g_w12[i] = fmaf(g_sigw[j], e[(long)s * ES + j], mu_w[j]);
    } else {
        int r = i - S * W12N;
        if (r < S * NB) {
            int s = r / NB, j = r % NB;
            g_ball[r] = fmaf(g_sigb[j], e[(long)s * ES + NW + j], mu_b[j]);
        }
    }
}

// ---------------- kernel 2: conv1 + bias + relu + maxpool ----------------
// grid = S*BATCH, block = 288. Thread: one pooled pixel (12x12) x 10 channels.
__global__ void __launch_bounds__(288) k_conv1(const float* __restrict__ x) {
    __shared__ float xs[784];
    __shared__ float ws[500];
    __shared__ float bs[20];
    int blk = blockIdx.x;
    int s = blk / BATCH, b = blk % BATCH;
    int t = threadIdx.x;
    for (int j = t; j < 784; j += 288) xs[j] = x[b * 784 + j];
    for (int j = t; j < 500; j += 288) ws[j] = g_w12[s * W12N + j];
    if (t < 20) bs[t] = g_ball[s * NB + t];
    __syncthreads();

    int pp = t % 144, cg = t / 144;          // cg in {0,1} -> channels cg*10..+9
    int pi = pp / 12, pj = pp % 12;
    float acc[10][4];
#pragma unroll
    for (int k = 0; k < 10; k++) { acc[k][0] = acc[k][1] = acc[k][2] = acc[k][3] = 0.0f; }

    const float* xb = xs + (2 * pi) * 28 + 2 * pj;
#pragma unroll 1
    for (int ky = 0; ky < 5; ky++) {
#pragma unroll
        for (int kx = 0; kx < 5; kx++) {
            float i00 = xb[ky * 28 + kx];
            float i01 = xb[ky * 28 + kx + 1];
            float i10 = xb[(ky + 1) * 28 + kx];
            float i11 = xb[(ky + 1) * 28 + kx + 1];
#pragma unroll
            for (int k = 0; k < 10; k++) {
                float wv = ws[(cg * 10 + k) * 25 + ky * 5 + kx];
                acc[k][0] = fmaf(wv, i00, acc[k][0]);
                acc[k][1] = fmaf(wv, i01, acc[k][1]);
                acc[k][2] = fmaf(wv, i10, acc[k][2]);
                acc[k][3] = fmaf(wv, i11, acc[k][3]);
            }
        }
    }
    float* outp = g_h1 + (long)(s * BATCH + b) * 2880;
#pragma unroll
    for (int k = 0; k < 10; k++) {
        int c = cg * 10 + k;
        float v = fmaxf(fmaxf(acc[k][0], acc[k][1]), fmaxf(acc[k][2], acc[k][3])) + bs[c];
        outp[c * 144 + pp] = fmaxf(v, 0.0f);
    }
}

// ---------------- kernel 3: conv2 + bias + relu + maxpool ----------------
// 4 batch images per block. grid = S*BATCH/4, block = 640 (160 per image, warp-aligned).
// smem: weights 25000 + bias 50 + pad + 4x input 2880 = 36576 floats (146 KB).
// Thread: one pooled pixel (4x4) x 5 output channels x 4 pool positions.
// Per input channel: 6x6 input patch cached in registers (36 LDS per 500 FMA group).
#define CV2_NB 4
#define CV2_SMEM_FLOATS (25056 + CV2_NB * 2880)
__global__ void __launch_bounds__(640) k_conv2() {
    extern __shared__ float sm[];
    float* ws  = sm;           // 25000
    float* bs  = sm + 25000;   // 50 (+6 pad)
    float* ins = sm + 25056;   // 4 * 2880
    int blk = blockIdx.x;
    int s = blk / (BATCH / CV2_NB);
    int b0 = (blk % (BATCH / CV2_NB)) * CV2_NB;
    int t = threadIdx.x;

    // cooperative loads (float4)
    {
        const float4* wp = (const float4*)(g_w12 + s * W12N + 500);
        float4* wd = (float4*)ws;
        for (int j = t; j < 6250; j += 640) wd[j] = wp[j];
        const float4* ip = (const float4*)(g_h1 + (long)(s * BATCH + b0) * 2880);
        float4* id = (float4*)ins;
        for (int j = t; j < CV2_NB * 720; j += 640) id[j] = ip[j];
        if (t < 50) bs[t] = g_ball[s * NB + 20 + t];
    }
    __syncthreads();

    int bl = t / 160;                 // image within block
    int r  = t % 160;
    int pp = r % 16, cg = r / 16;     // cg in 0..9 -> channels cg*5..+4
    int pi = pp / 4, pj = pp % 4;
    float acc[5][4];
#pragma unroll
    for (int k = 0; k < 5; k++) { acc[k][0] = acc[k][1] = acc[k][2] = acc[k][3] = 0.0f; }

    const float* ib = ins + bl * 2880 + (2 * pi) * 12 + 2 * pj;
    const float* wb = ws + cg * 5 * 500;
#pragma unroll 1
    for (int ci = 0; ci < 20; ci++) {
        // cache 6x6 input patch in registers
        float p[6][6];
        const float* ic = ib + ci * 144;
#pragma unroll
        for (int yy = 0; yy < 6; yy++)
#pragma unroll
            for (int xx = 0; xx < 6; xx++)
                p[yy][xx] = ic[yy * 12 + xx];

        const float* wc = wb + ci * 25;
#pragma unroll
        for (int ky = 0; ky < 5; ky++) {
#pragma unroll
            for (int kx = 0; kx < 5; kx++) {
                float i00 = p[ky][kx];
                float i01 = p[ky][kx + 1];
                float i10 = p[ky + 1][kx];
                float i11 = p[ky + 1][kx + 1];
                int wo = ky * 5 + kx;
#pragma unroll
                for (int k = 0; k < 5; k++) {
                    float wv = wc[k * 500 + wo];
                    acc[k][0] = fmaf(wv, i00, acc[k][0]);
                    acc[k][1] = fmaf(wv, i01, acc[k][1]);
                    acc[k][2] = fmaf(wv, i10, acc[k][2]);
                    acc[k][3] = fmaf(wv, i11, acc[k][3]);
                }
            }
        }
    }
    float* outp = g_h2 + (long)(s * BATCH + b0 + bl) * 800;
#pragma unroll
    for (int k = 0; k < 5; k++) {
        int co = cg * 5 + k;
        float v = fmaxf(fmaxf(acc[k][0], acc[k][1]), fmaxf(acc[k][2], acc[k][3])) + bs[co];
        outp[co * 16 + pi * 4 + pj] = fmaxf(v, 0.0f);
    }
}

// ---------------- kernel 4: fc1 (500x800 @ 800x128) + bias + relu ----------------
// grid = (8 mtiles, S), block = 256. BM=64, BN=128, BK=8, thread tile 4x8.
// A generated on the fly: w3 = mu + sig*e. Register double-buffered global loads.
__global__ void __launch_bounds__(256) k_fc1(const float* __restrict__ e,
                                             const float* __restrict__ mu_w) {
    __shared__ float As[8][68];   // padded: transposed A tile [k][m]
    __shared__ float Bs[8][128];  // B tile [k][n]
    int s = blockIdx.y;
    int mt = blockIdx.x;
    int tid = threadIdx.x;
    int tx = tid % 16, ty = tid / 16;
    int m0 = mt * 64;

    const float* eb = e + (long)s * ES + WOFF2;

    int la = tid * 2;              // A: 512 elems, 2 per thread
    int am = la / 8, ak = la % 8;  // (m-local, k-local), ak even
    int bn = tid / 2, bq = (tid % 2) * 4;  // B: one float4 per thread

    float ra0, ra1;
    float rb0, rb1, rb2, rb3;
    {
        int grow = m0 + am;
        if (grow < 500) {
            long ai = (long)grow * 800 + ak;
            ra0 = fmaf(g_sigw[WOFF2 + ai], eb[ai], mu_w[WOFF2 + ai]);
            ra1 = fmaf(g_sigw[WOFF2 + ai + 1], eb[ai + 1], mu_w[WOFF2 + ai + 1]);
        } else { ra0 = 0.0f; ra1 = 0.0f; }
        float4 bv = *(const float4*)(g_h2 + ((long)s * BATCH + bn) * 800 + bq);
        rb0 = bv.x; rb1 = bv.y; rb2 = bv.z; rb3 = bv.w;
    }

    float acc[4][8];
#pragma unroll
    for (int i = 0; i < 4; i++)
#pragma unroll
        for (int j = 0; j < 8; j++) acc[i][j] = 0.0f;

    for (int kt = 0; kt < 100; kt++) {
        As[ak][am] = ra0;
        As[ak + 1][am] = ra1;
        Bs[bq + 0][bn] = rb0;
        Bs[bq + 1][bn] = rb1;
        Bs[bq + 2][bn] = rb2;
        Bs[bq + 3][bn] = rb3;
        __syncthreads();

        if (kt < 99) {
            int k0 = (kt + 1) * 8;
            int grow = m0 + am;
            if (grow < 500) {
                long ai = (long)grow * 800 + k0 + ak;
                ra0 = fmaf(g_sigw[WOFF2 + ai], eb[ai], mu_w[WOFF2 + ai]);
                ra1 = fmaf(g_sigw[WOFF2 + ai + 1], eb[ai + 1], mu_w[WOFF2 + ai + 1]);
            } else { ra0 = 0.0f; ra1 = 0.0f; }
            float4 bv = *(const float4*)(g_h2 + ((long)s * BATCH + bn) * 800 + k0 + bq);
            rb0 = bv.x; rb1 = bv.y; rb2 = bv.z; rb3 = bv.w;
        }

#pragma unroll
        for (int k = 0; k < 8; k++) {
            float a[4], bb[8];
            *(float4*)a = *(const float4*)&As[k][ty * 4];
            *(float4*)bb = *(const float4*)&Bs[k][tx * 8];
            *(float4*)(bb + 4) = *(const float4*)&Bs[k][tx * 8 + 4];
#pragma unroll
            for (int i = 0; i < 4; i++)
#pragma unroll
                for (int j = 0; j < 8; j++)
                    acc[i][j] = fmaf(a[i], bb[j], acc[i][j]);
        }
        __syncthreads();
    }

#pragma unroll
    for (int i = 0; i < 4; i++) {
        int m = m0 + ty * 4 + i;
        if (m < 500) {
            float bias = g_ball[s * NB + 70 + m];
            float* op = g_h3 + ((long)s * 500 + m) * BATCH + tx * 8;
#pragma unroll
            for (int j = 0; j < 8; j++) {
                op[j] = fmaxf(acc[i][j] + bias, 0.0f);
            }
        }
    }
}

// ---------------- kernel 5: fc2 + bias + log_softmax ----------------
// grid = S, block = 128 (one thread per batch element).
__global__ void __launch_bounds__(128) k_fc2(const float* __restrict__ e,
                                             const float* __restrict__ mu_w) {
    __shared__ float ws[5000];
    __shared__ float bs[10];
    int s = blockIdx.x;
    int t = threadIdx.x;
    for (int j = t; j < 5000; j += 128) {
        long gi = (long)WOFF3 + j;
        ws[j] = fmaf(g_sigw[gi], e[(long)s * ES + gi], mu_w[gi]);
    }
    if (t < 10) bs[t] = g_ball[s * NB + 570 + t];
    __syncthreads();

    float acc[10];
#pragma unroll
    for (int o = 0; o < 10; o++) acc[o] = bs[o];

    const float* hp = g_h3 + (long)s * 500 * BATCH + t;
    for (int i = 0; i < 500; i++) {
        float v = hp[(long)i * BATCH];
#pragma unroll
        for (int o = 0; o < 10; o++) acc[o] = fmaf(ws[o * 500 + i], v, acc[o]);
    }

    float m = acc[0];
#pragma unroll
    for (int o = 1; o < 10; o++) m = fmaxf(m, acc[o]);
    float sum = 0.0f;
#pragma unroll
    for (int o = 0; o < 10; o++) sum += expf(acc[o] - m);
    float lse = m + logf(sum);

    float* op = g_lsm + ((long)s * BATCH + t) * 10;
#pragma unroll
    for (int o = 0; o < 10; o++) op[o] = acc[o] - lse;
}

// ---------------- kernel 6: deterministic mean over samples ----------------
__global__ void k_reduce(float* __restrict__ out) {
    int idx = blockIdx.x * blockDim.x + threadIdx.x;
    if (idx >= BATCH * 10) return;
    int b = idx / 10, o = idx % 10;
    float acc = 0.0f;
    for (int s = 0; s < S; s++) acc += g_lsm[((long)s * BATCH + b) * 10 + o];
    out[idx] = acc * (1.0f / (float)S);
}

// ---------------- launch ----------------
extern "C" void kernel_launch(void* const* d_in, const int* in_sizes, int n_in,
                              void* d_out, int out_size) {
    const float* x     = (const float*)d_in[0];
    const float* e     = (const float*)d_in[1];
    const float* mu_w  = (const float*)d_in[2];
    const float* rho_w = (const float*)d_in[3];
    const float* mu_b  = (const float*)d_in[4];
    const float* rho_b = (const float*)d_in[5];
    float* out = (float*)d_out;

    static int smem_set = 0;
    if (!smem_set) {
        cudaFuncSetAttribute(k_conv2, cudaFuncAttributeMaxDynamicSharedMemorySize,
                             CV2_SMEM_FLOATS * 4);
        smem_set = 1;
    }

    k_sig<<<(ES + 255) / 256, 256>>>(rho_w, rho_b);

    int wb_total = S * W12N + S * NB;
    k_wb<<<(wb_total + 255) / 256, 256>>>(e, mu_w, mu_b);

    k_conv1<<<S * BATCH, 288>>>(x);
    k_conv2<<<S * BATCH / CV2_NB, 640, CV2_SMEM_FLOATS * 4>>>();

    dim3 g1(8, S);
    k_fc1<<<g1, 256>>>(e, mu_w);
    k_fc2<<<S, 128>>>(e, mu_w);
    k_reduce<<<10, 128>>>(out);
}

// round 4
// speedup vs baseline: 1.4587x; 1.0047x over previous
#include <cuda_runtime.h>
#include <math.h>

#define S 100
#define BATCH 128
#define NW 430500
#define NB 580
#define ES (NW + NB)
#define W12N 25500
#define WOFF2 25500
#define WOFF3 425500

// ---------------- scratch (device globals; no runtime allocation) ----------------
__device__ float g_sigw[NW];
__device__ float g_sigb[NB];
__device__ float g_w1[S * 500];          // per-sample conv1 weights
__device__ float g_w2p[S * 28000];       // per-sample conv2 weights, [ch50][ci20][28pad]
__device__ float g_ball[S * NB];         // per-sample all biases
__device__ float g_h1[S * BATCH * 2880]; // after conv1+relu+pool: [s][b][20][12][12]
__device__ float g_h2[S * BATCH * 800];  // after conv2+relu+pool: [s][b][800] (c*16+y*4+x)
__device__ float g_h3[S * 500 * BATCH];  // after fc1+relu: [s][500][128]
__device__ float g_lsm[S * BATCH * 10];  // per-sample log-softmax

__device__ __forceinline__ float softplusf(float r) {
    return fmaxf(r, 0.0f) + log1pf(expf(-fabsf(r)));
}

// ---------------- kernel 0: softplus(rho) ----------------
__global__ void k_sig(const float* __restrict__ rho_w, const float* __restrict__ rho_b) {
    int i = blockIdx.x * blockDim.x + threadIdx.x;
    if (i < NW) g_sigw[i] = softplusf(rho_w[i]);
    else if (i < NW + NB) g_sigb[i - NW] = softplusf(rho_b[i - NW]);
}

// ---------------- kernel 1: materialize conv weights (repacked) + biases ----------------
__global__ void k_wb(const float* __restrict__ e,
                     const float* __restrict__ mu_w,
                     const float* __restrict__ mu_b) {
    int i = blockIdx.x * blockDim.x + threadIdx.x;
    if (i < S * W12N) {
        int s = i / W12N, j = i % W12N;
        float v = fmaf(g_sigw[j], e[(long)s * ES + j], mu_w[j]);
        if (j < 500) {
            g_w1[s * 500 + j] = v;
        } else {
            int jj = j - 500;
            int ch = jj / 500;
            int r = jj % 500;
            int ci = r / 25, wo = r % 25;
            g_w2p[s * 28000 + ch * 560 + ci * 28 + wo] = v;
        }
    } else {
        int r = i - S * W12N;
        if (r < S * NB) {
            int s = r / NB, j = r % NB;
            g_ball[r] = fmaf(g_sigb[j], e[(long)s * ES + NW + j], mu_b[j]);
        }
    }
}

// ---------------- kernel 2: conv1 + bias + relu + maxpool ----------------
// grid = S*BATCH, block = 288. Thread: one pooled pixel (12x12) x 10 channels.
__global__ void __launch_bounds__(288) k_conv1(const float* __restrict__ x) {
    __shared__ float xs[784];
    __shared__ float ws[500];
    __shared__ float bs[20];
    int blk = blockIdx.x;
    int s = blk / BATCH, b = blk % BATCH;
    int t = threadIdx.x;
    for (int j = t; j < 784; j += 288) xs[j] = x[b * 784 + j];
    for (int j = t; j < 500; j += 288) ws[j] = g_w1[s * 500 + j];
    if (t < 20) bs[t] = g_ball[s * NB + t];
    __syncthreads();

    int pp = t % 144, cg = t / 144;          // cg in {0,1} -> channels cg*10..+9
    int pi = pp / 12, pj = pp % 12;
    float acc[10][4];
#pragma unroll
    for (int k = 0; k < 10; k++) { acc[k][0] = acc[k][1] = acc[k][2] = acc[k][3] = 0.0f; }

    const float* xb = xs + (2 * pi) * 28 + 2 * pj;
#pragma unroll 1
    for (int ky = 0; ky < 5; ky++) {
#pragma unroll
        for (int kx = 0; kx < 5; kx++) {
            float i00 = xb[ky * 28 + kx];
            float i01 = xb[ky * 28 + kx + 1];
            float i10 = xb[(ky + 1) * 28 + kx];
            float i11 = xb[(ky + 1) * 28 + kx + 1];
#pragma unroll
            for (int k = 0; k < 10; k++) {
                float wv = ws[(cg * 10 + k) * 25 + ky * 5 + kx];
                acc[k][0] = fmaf(wv, i00, acc[k][0]);
                acc[k][1] = fmaf(wv, i01, acc[k][1]);
                acc[k][2] = fmaf(wv, i10, acc[k][2]);
                acc[k][3] = fmaf(wv, i11, acc[k][3]);
            }
        }
    }
    float* outp = g_h1 + (long)(s * BATCH + b) * 2880;
#pragma unroll
    for (int k = 0; k < 10; k++) {
        int c = cg * 10 + k;
        float v = fmaxf(fmaxf(acc[k][0], acc[k][1]), fmaxf(acc[k][2], acc[k][3])) + bs[c];
        outp[c * 144 + pp] = fmaxf(v, 0.0f);
    }
}

// ---------------- kernel 3: conv2 + bias + relu + maxpool ----------------
// 4 images/block, block = 640 (160 per image). smem: w2p 28000 + bias 56 + ins 4*2880.
// Weights padded [ch][ci][28] -> 6x LDS.128 + 1 scalar per (ch,ci).
// Patch rows loaded as float2. Issue budget per ci: 18+35 LDS + 250 FMA slots.
#define CV2_NB 4
#define CV2_SMEM_FLOATS (28056 + CV2_NB * 2880)
__global__ void __launch_bounds__(640) k_conv2() {
    extern __shared__ float sm[];
    float* ws  = sm;           // 28000 (padded weights)
    float* bs  = sm + 28000;   // 50 (+6 pad)
    float* ins = sm + 28056;   // 4 * 2880
    int blk = blockIdx.x;
    int s = blk / (BATCH / CV2_NB);
    int b0 = (blk % (BATCH / CV2_NB)) * CV2_NB;
    int t = threadIdx.x;

    // cooperative loads (float4)
    {
        const float4* wp = (const float4*)(g_w2p + s * 28000);
        float4* wd = (float4*)ws;
        for (int j = t; j < 7000; j += 640) wd[j] = wp[j];
        const float4* ip = (const float4*)(g_h1 + (long)(s * BATCH + b0) * 2880);
        float4* id = (float4*)ins;
        for (int j = t; j < CV2_NB * 720; j += 640) id[j] = ip[j];
        if (t < 50) bs[t] = g_ball[s * NB + 20 + t];
    }
    __syncthreads();

    int bl = t / 160;                 // image within block
    int r  = t % 160;
    int pp = r % 16, cg = r / 16;     // cg in 0..9 -> channels cg*5..+4
    int pi = pp / 4, pj = pp % 4;
    float acc[5][4];
#pragma unroll
    for (int k = 0; k < 5; k++) { acc[k][0] = acc[k][1] = acc[k][2] = acc[k][3] = 0.0f; }

    const float* ib = ins + bl * 2880 + (2 * pi) * 12 + 2 * pj;
    const float* wbase = ws + cg * 5 * 560;   // 5 channels, stride 560
#pragma unroll 1
    for (int ci = 0; ci < 20; ci++) {
        // cache 6x6 input patch in registers (float2 rows)
        float p[6][6];
        const float* ic = ib + ci * 144;
#pragma unroll
        for (int yy = 0; yy < 6; yy++) {
            float2 a = *(const float2*)(ic + yy * 12);
            float2 c = *(const float2*)(ic + yy * 12 + 2);
            float2 d = *(const float2*)(ic + yy * 12 + 4);
            p[yy][0] = a.x; p[yy][1] = a.y;
            p[yy][2] = c.x; p[yy][3] = c.y;
            p[yy][4] = d.x; p[yy][5] = d.y;
        }

#pragma unroll
        for (int k = 0; k < 5; k++) {
            const float* wc = wbase + k * 560 + ci * 28;
            const float4* wc4 = (const float4*)wc;
#pragma unroll
            for (int kg = 0; kg < 6; kg++) {
                float4 wv = wc4[kg];
                float wa[4] = {wv.x, wv.y, wv.z, wv.w};
#pragma unroll
                for (int q = 0; q < 4; q++) {
                    int wo = kg * 4 + q;
                    int ky = wo / 5, kx = wo % 5;
                    acc[k][0] = fmaf(wa[q], p[ky][kx],       acc[k][0]);
                    acc[k][1] = fmaf(wa[q], p[ky][kx + 1],   acc[k][1]);
                    acc[k][2] = fmaf(wa[q], p[ky + 1][kx],   acc[k][2]);
                    acc[k][3] = fmaf(wa[q], p[ky + 1][kx + 1], acc[k][3]);
                }
            }
            float w24 = wc[24];   // wo = 24 -> ky=4, kx=4
            acc[k][0] = fmaf(w24, p[4][4], acc[k][0]);
            acc[k][1] = fmaf(w24, p[4][5], acc[k][1]);
            acc[k][2] = fmaf(w24, p[5][4], acc[k][2]);
            acc[k][3] = fmaf(w24, p[5][5], acc[k][3]);
        }
    }
    float* outp = g_h2 + (long)(s * BATCH + b0 + bl) * 800;
#pragma unroll
    for (int k = 0; k < 5; k++) {
        int co = cg * 5 + k;
        float v = fmaxf(fmaxf(acc[k][0], acc[k][1]), fmaxf(acc[k][2], acc[k][3])) + bs[co];
        outp[co * 16 + pi * 4 + pj] = fmaxf(v, 0.0f);
    }
}

// ---------------- kernel 4: fc1 (500x800 @ 800x128) + bias + relu ----------------
// grid = (8 mtiles, S), block = 256. BM=64, BN=128, BK=8, thread tile 4x8.
__global__ void __launch_bounds__(256) k_fc1(const float* __restrict__ e,
                                             const float* __restrict__ mu_w) {
    __shared__ float As[8][68];   // padded: transposed A tile [k][m]
    __shared__ float Bs[8][128];  // B tile [k][n]
    int s = blockIdx.y;
    int mt = blockIdx.x;
    int tid = threadIdx.x;
    int tx = tid % 16, ty = tid / 16;
    int m0 = mt * 64;

    const float* eb = e + (long)s * ES + WOFF2;

    int la = tid * 2;              // A: 512 elems, 2 per thread
    int am = la / 8, ak = la % 8;  // (m-local, k-local), ak even
    int bn = tid / 2, bq = (tid % 2) * 4;  // B: one float4 per thread

    float ra0, ra1;
    float rb0, rb1, rb2, rb3;
    {
        int grow = m0 + am;
        if (grow < 500) {
            long ai = (long)grow * 800 + ak;
            ra0 = fmaf(g_sigw[WOFF2 + ai], eb[ai], mu_w[WOFF2 + ai]);
            ra1 = fmaf(g_sigw[WOFF2 + ai + 1], eb[ai + 1], mu_w[WOFF2 + ai + 1]);
        } else { ra0 = 0.0f; ra1 = 0.0f; }
        float4 bv = *(const float4*)(g_h2 + ((long)s * BATCH + bn) * 800 + bq);
        rb0 = bv.x; rb1 = bv.y; rb2 = bv.z; rb3 = bv.w;
    }

    float acc[4][8];
#pragma unroll
    for (int i = 0; i < 4; i++)
#pragma unroll
        for (int j = 0; j < 8; j++) acc[i][j] = 0.0f;

    for (int kt = 0; kt < 100; kt++) {
        As[ak][am] = ra0;
        As[ak + 1][am] = ra1;
        Bs[bq + 0][bn] = rb0;
        Bs[bq + 1][bn] = rb1;
        Bs[bq + 2][bn] = rb2;
        Bs[bq + 3][bn] = rb3;
        __syncthreads();

        if (kt < 99) {
            int k0 = (kt + 1) * 8;
            int grow = m0 + am;
            if (grow < 500) {
                long ai = (long)grow * 800 + k0 + ak;
                ra0 = fmaf(g_sigw[WOFF2 + ai], eb[ai], mu_w[WOFF2 + ai]);
                ra1 = fmaf(g_sigw[WOFF2 + ai + 1], eb[ai + 1], mu_w[WOFF2 + ai + 1]);
            } else { ra0 = 0.0f; ra1 = 0.0f; }
            float4 bv = *(const float4*)(g_h2 + ((long)s * BATCH + bn) * 800 + k0 + bq);
            rb0 = bv.x; rb1 = bv.y; rb2 = bv.z; rb3 = bv.w;
        }

#pragma unroll
        for (int k = 0; k < 8; k++) {
            float a[4], bb[8];
            *(float4*)a = *(const float4*)&As[k][ty * 4];
            *(float4*)bb = *(const float4*)&Bs[k][tx * 8];
            *(float4*)(bb + 4) = *(const float4*)&Bs[k][tx * 8 + 4];
#pragma unroll
            for (int i = 0; i < 4; i++)
#pragma unroll
                for (int j = 0; j < 8; j++)
                    acc[i][j] = fmaf(a[i], bb[j], acc[i][j]);
        }
        __syncthreads();
    }

#pragma unroll
    for (int i = 0; i < 4; i++) {
        int m = m0 + ty * 4 + i;
        if (m < 500) {
            float bias = g_ball[s * NB + 70 + m];
            float* op = g_h3 + ((long)s * 500 + m) * BATCH + tx * 8;
#pragma unroll
            for (int j = 0; j < 8; j++) {
                op[j] = fmaxf(acc[i][j] + bias, 0.0f);
            }
        }
    }
}

// ---------------- kernel 5: fc2 + bias + log_softmax ----------------
__global__ void __launch_bounds__(128) k_fc2(const float* __restrict__ e,
                                             const float* __restrict__ mu_w) {
    __shared__ float ws[5000];
    __shared__ float bs[10];
    int s = blockIdx.x;
    int t = threadIdx.x;
    for (int j = t; j < 5000; j += 128) {
        long gi = (long)WOFF3 + j;
        ws[j] = fmaf(g_sigw[gi], e[(long)s * ES + gi], mu_w[gi]);
    }
    if (t < 10) bs[t] = g_ball[s * NB + 570 + t];
    __syncthreads();

    float acc[10];
#pragma unroll
    for (int o = 0; o < 10; o++) acc[o] = bs[o];

    const float* hp = g_h3 + (long)s * 500 * BATCH + t;
    for (int i = 0; i < 500; i++) {
        float v = hp[(long)i * BATCH];
#pragma unroll
        for (int o = 0; o < 10; o++) acc[o] = fmaf(ws[o * 500 + i], v, acc[o]);
    }

    float m = acc[0];
#pragma unroll
    for (int o = 1; o < 10; o++) m = fmaxf(m, acc[o]);
    float sum = 0.0f;
#pragma unroll
    for (int o = 0; o < 10; o++) sum += expf(acc[o] - m);
    float lse = m + logf(sum);

    float* op = g_lsm + ((long)s * BATCH + t) * 10;
#pragma unroll
    for (int o = 0; o < 10; o++) op[o] = acc[o] - lse;
}

// ---------------- kernel 6: deterministic mean over samples ----------------
__global__ void k_reduce(float* __restrict__ out) {
    int idx = blockIdx.x * blockDim.x + threadIdx.x;
    if (idx >= BATCH * 10) return;
    int b = idx / 10, o = idx % 10;
    float acc = 0.0f;
    for (int s = 0; s < S; s++) acc += g_lsm[((long)s * BATCH + b) * 10 + o];
    out[idx] = acc * (1.0f / (float)S);
}

// ---------------- launch ----------------
extern "C" void kernel_launch(void* const* d_in, const int* in_sizes, int n_in,
                              void* d_out, int out_size) {
    const float* x     = (const float*)d_in[0];
    const float* e     = (const float*)d_in[1];
    const float* mu_w  = (const float*)d_in[2];
    const float* rho_w = (const float*)d_in[3];
    const float* mu_b  = (const float*)d_in[4];
    const float* rho_b = (const float*)d_in[5];
    float* out = (float*)d_out;

    static int smem_set = 0;
    if (!smem_set) {
        cudaFuncSetAttribute(k_conv2, cudaFuncAttributeMaxDynamicSharedMemorySize,
                             CV2_SMEM_FLOATS * 4);
        smem_set = 1;
    }

    k_sig<<<(ES + 255) / 256, 256>>>(rho_w, rho_b);

    int wb_total = S * W12N + S * NB;
    k_wb<<<(wb_total + 255) / 256, 256>>>(e, mu_w, mu_b);

    k_conv1<<<S * BATCH, 288>>>(x);
    k_conv2<<<S * BATCH / CV2_NB, 640, CV2_SMEM_FLOATS * 4>>>();

    dim3 g1(8, S);
    k_fc1<<<g1, 256>>>(e, mu_w);
    k_fc2<<<S, 128>>>(e, mu_w);
    k_reduce<<<10, 128>>>(out);
}